// round 11
// baseline (speedup 1.0000x reference)
#include <cuda_runtime.h>

#define EPS 1e-6f
typedef unsigned long long u64t;

#define MUL2(d,a,b)    asm("mul.rn.f32x2 %0, %1, %2;" : "=l"(d) : "l"(a), "l"(b))
#define FMA2(d,a,b,c)  asm("fma.rn.f32x2 %0, %1, %2, %3;" : "=l"(d) : "l"(a), "l"(b), "l"(c))
#define PACK2(d,lo,hi) asm("mov.b64 %0, {%1, %2};" : "=l"(d) : "f"(lo), "f"(hi))
#define UNPACK2(lo,hi,s) asm("mov.b64 {%0, %1}, %2;" : "=f"(lo), "=f"(hi) : "l"(s))

// Scratch (device global: no allocation allowed)
__device__ float g_xr[256*128*64];     // xr in BINARY blade order, 8 MB

// ---------------------------------------------------------------------------
// Compile-time blade-ordering tables (input-independent, N_GEN=6 fixed).
struct Tab { int b2s[64]; int s2c[64]; int c2b[64]; int qcls[16]; };

constexpr int popc_c(int v) { int c = 0; while (v) { c += v & 1; v >>= 1; } return c; }

constexpr Tab make_tab() {
    Tab T{};
    int s_of_b[64] = {};
    for (int b = 0; b < 64; b++) {
        int pc = popc_c(b), rank = 0;
        for (int u = 0; u < 64; u++) {
            int pu = popc_c(u);
            if (pu < pc || (pu == pc && u < b)) rank++;
        }
        s_of_b[b] = rank;
        T.b2s[b] = rank;
    }
    for (int b = 0; b < 64; b++) {
        int c = popc_c(b) & 3, s = s_of_b[b], co = 0;
        for (int u = 0; u < 64; u++) {
            int cu = popc_c(u) & 3;
            if (cu < c || (cu == c && s_of_b[u] < s)) co++;
        }
        T.s2c[s] = co;
        T.c2b[co] = b;
        if ((co & 3) == 0) T.qcls[co >> 2] = c;
    }
    return T;
}

__constant__ Tab d_tab = make_tab();

// ---------------------------------------------------------------------------
// Kernel 1: linear mix + bias + class-norm gate, f32x2 over m-pairs.
// grid 1024 = (b:256) x (nt:4 of 32 n), block 256.
// x staged in smem (class-sorted pad-swizzle); w read DIRECTLY from w_lin
// as 4x LDG.32 + PACK2 per m-pair (L2-resident; hidden under fma pipe).
// smem = x tile only (35 KB) -> 4 blocks/SM.
__global__ __launch_bounds__(256, 4) void k_linear(
    const float* __restrict__ x, const float* __restrict__ w_lin,
    const float* __restrict__ b_lin, const float* __restrict__ a_norm) {
    extern __shared__ float sm[];
    __shared__ int ss2c[64], sc2b[64], sq[16];
    int t = threadIdx.x;
    int b = blockIdx.x >> 2, nt = blockIdx.x & 3;
    if (t < 64) { ss2c[t] = d_tab.s2c[t]; sc2b[t] = d_tab.c2b[t]; }
    if (t >= 64 && t < 80) sq[t - 64] = d_tab.qcls[t - 64];
    __syncthreads();   // ss2c needed for staging

    // stage x with class-sort + pad-swizzle transpose
    {
        const float4* xg = (const float4*)(x + (size_t)b*8192);
        #pragma unroll
        for (int r = 0; r < 8; r++) {
            int idx4 = t + 256*r;
            float4 v = xg[idx4];
            int m = idx4 >> 4, s0 = (idx4 & 15)*4;
            int mp = m >> 1, par = m & 1;
            int co;
            co = ss2c[s0+0]; sm[mp*140 + co*2 + par + ((co>>4)<<2)] = v.x;
            co = ss2c[s0+1]; sm[mp*140 + co*2 + par + ((co>>4)<<2)] = v.y;
            co = ss2c[s0+2]; sm[mp*140 + co*2 + par + ((co>>4)<<2)] = v.z;
            co = ss2c[s0+3]; sm[mp*140 + co*2 + par + ((co>>4)<<2)] = v.w;
        }
    }
    __syncthreads();

    int ig = t & 15, nh = (t >> 4) & 7, qh = t >> 7;
    int c = sq[ig];
    const ulonglong2* px = (const ulonglong2*)sm + ig*2 + (ig >> 2);
    // direct w_lin pointers: slotA = nh + 16*qh, slotB = slotA + 8
    const float* pw0 = w_lin + (nt*32 + nh + 16*qh)*512 + c;
    const float* pw1 = pw0 + 8*512;

    u64t acc[2][4];
    #pragma unroll
    for (int q = 0; q < 2; q++)
        #pragma unroll
        for (int d = 0; d < 4; d++) acc[q][d] = 0ull;

    #pragma unroll
    for (int mp = 0; mp < 64; mp++) {
        ulonglong2 xa = px[mp*35];
        ulonglong2 xb = px[mp*35 + 1];
        float w0lo = pw0[8*mp],     w0hi = pw0[8*mp + 4];
        float w1lo = pw1[8*mp],     w1hi = pw1[8*mp + 4];
        u64t w0, w1;
        PACK2(w0, w0lo, w0hi);
        PACK2(w1, w1lo, w1hi);
        FMA2(acc[0][0], xa.x, w0, acc[0][0]);
        FMA2(acc[0][1], xa.y, w0, acc[0][1]);
        FMA2(acc[0][2], xb.x, w0, acc[0][2]);
        FMA2(acc[0][3], xb.y, w0, acc[0][3]);
        FMA2(acc[1][0], xa.x, w1, acc[1][0]);
        FMA2(acc[1][1], xa.y, w1, acc[1][1]);
        FMA2(acc[1][2], xb.x, w1, acc[1][2]);
        FMA2(acc[1][3], xb.y, w1, acc[1][3]);
    }

    float f[2][4];
    #pragma unroll
    for (int q = 0; q < 2; q++)
        #pragma unroll
        for (int d = 0; d < 4; d++) {
            float lo, hi; UNPACK2(lo, hi, acc[q][d]);
            f[q][d] = lo + hi;
        }
    int n0 = nt*32 + nh + 16*qh;
    if (ig == 0) { f[0][0] += b_lin[n0]; f[1][0] += b_lin[n0 + 8]; }

    float v[2][4];
    #pragma unroll
    for (int q = 0; q < 2; q++) {
        float s = f[q][0]*f[q][0] + f[q][1]*f[q][1]
                + f[q][2]*f[q][2] + f[q][3]*f[q][3];
        #pragma unroll
        for (int cc = 0; cc < 4; cc++) v[q][cc] = (c == cc) ? s : 0.f;
    }
    #pragma unroll
    for (int off = 8; off; off >>= 1) {
        #pragma unroll
        for (int q = 0; q < 2; q++)
            #pragma unroll
            for (int cc = 0; cc < 4; cc++)
                v[q][cc] += __shfl_xor_sync(0xffffffffu, v[q][cc], off);
    }
    #pragma unroll
    for (int q = 0; q < 2; q++) {
        int n = n0 + 8*q;
        float vv = (c==0)?v[q][0]:(c==1)?v[q][1]:(c==2)?v[q][2]:v[q][3];
        float gg = 1.f/(1.f + expf(-a_norm[n*4 + c]));
        float inv = 1.f/(gg*(sqrtf(vv) - 1.f) + 1.f + EPS);
        float* o = g_xr + (size_t)b*8192 + (size_t)n*64;
        o[sc2b[ig*4+0]] = f[q][0]*inv;
        o[sc2b[ig*4+1]] = f[q][1]*inv;
        o[sc2b[ig*4+2]] = f[q][2]*inv;
        o[sc2b[ig*4+3]] = f[q][3]*inv;
    }
}

// ---------------------------------------------------------------------------
// Kernel 2: out[b,n,j] = sum_k coef[n][k][j] * x[b,n,j^k] * xr[b,n,k]
// grid (n:128, jh:2, bg:4), block 256 = 8 warps.
// warp w: j-octet = jh*4 + (w&3); ko range = (w>>2)*4 .. +3.
// Warp pairs (w, w+4) each cover half the k-sum; merged via smem at the end.
// smem words: Cs2 dup pairs (j-half) [0,4096); Rp [4096,8320): k*66+2bp;
//             Xp [8320,12544): i*66+2bp.  50.2 KB.
__global__ __launch_bounds__(256, 4) void k_bilinear(
    const float* __restrict__ x, const float* __restrict__ w_gp,
    const int* __restrict__ pidx, int P, float* __restrict__ out) {
    extern __shared__ float sm[];
    __shared__ int sjb[64];
    __shared__ float f4[64];
    int n = blockIdx.x, jh = blockIdx.y, bg = blockIdx.z;
    int t = threadIdx.x;
    if (t < 64) { sjb[t] = d_tab.b2s[t]; f4[t] = 0.f; }
    __syncthreads();

    // fill f4 from paths + stage x/xr (sjb ready)
    for (int p = t; p < P; p += 256) {
        int code = pidx[3*p]*16 + pidx[3*p+1]*4 + pidx[3*p+2];
        f4[code] = w_gp[n*P + p];
    }
    #pragma unroll
    for (int r = 0; r < 8; r++) {
        int p = t + 256*r;
        int i = p & 63, bq = p >> 6;
        size_t gb = (size_t)(bg*64 + 2*bq)*8192 + (size_t)n*64;
        int s = sjb[i];
        float xl = x[gb + s],      xh = x[gb + 8192 + s];
        float rl = g_xr[gb + i],   rh = g_xr[gb + 8192 + i];
        u64t pxv, prv; PACK2(pxv, xl, xh); PACK2(prv, rl, rh);
        *(u64t*)(sm + 8320 + i*66 + 2*bq) = pxv;
        *(u64t*)(sm + 4096 + i*66 + 2*bq) = prv;
    }
    __syncthreads();

    // compute coef dup-pairs for this j-half (reads f4, writes [0,4096) words)
    u64t* Cs2 = (u64t*)sm;
    #pragma unroll
    for (int r = 0; r < 8; r++) {
        int idx = t + 256*r;                 // idx = k*32 + jl
        int k = idx >> 5, jl = idx & 31;
        int j = jh*32 + jl, i = j ^ k;
        int h = (i>>1) ^ (i>>2) ^ (i>>3) ^ (i>>4) ^ (i>>5);
        float sgn = (__popc(h & k) & 1) ? -1.f : 1.f;
        int code = (__popc(i)&3)*16 + (__popc(j)&3)*4 + (__popc(k)&3);
        float c = sgn * f4[code];
        u64t pc; PACK2(pc, c, c);
        Cs2[idx] = pc;
    }
    __syncthreads();

    int lane = t & 31, w = t >> 5;
    int joL = w & 3;                 // local j-octet within half
    int jog = jh*4 + joL;            // global j-octet
    int kb = (w >> 2)*4;             // ko range start
    const u64t* pR = (const u64t*)sm + 2048 + lane;   // + k*33
    const u64t* pX = (const u64t*)sm + 4160 + lane;   // + i*33
    const ulonglong2* pC = (const ulonglong2*)sm;     // + k*16 + joL*4 + jp

    u64t acc[8];
    #pragma unroll
    for (int jj = 0; jj < 8; jj++) acc[jj] = 0ull;

    #pragma unroll
    for (int kt = 0; kt < 4; kt++) {
        int ko = kb + kt;
        int io = jog ^ ko;
        u64t xv[8];
        #pragma unroll
        for (int d = 0; d < 8; d++) xv[d] = pX[(io*8 + d)*33];
        #pragma unroll
        for (int kk = 0; kk < 8; kk++) {
            u64t rv = pR[(ko*8 + kk)*33];
            const ulonglong2* pCk = pC + (ko*8 + kk)*16 + joL*4;
            #pragma unroll
            for (int jp = 0; jp < 4; jp++) {
                ulonglong2 cc = pCk[jp];
                u64t t0, t1;
                MUL2(t0, xv[(2*jp)^kk], rv);
                FMA2(acc[2*jp], cc.x, t0, acc[2*jp]);
                MUL2(t1, xv[(2*jp+1)^kk], rv);
                FMA2(acc[2*jp+1], cc.y, t1, acc[2*jp+1]);
            }
        }
    }
    __syncthreads();
    // two partial buffers: warps 0-3 -> [0,2240), warps 4-7 -> [2240,4480)
    {
        float* Ow = sm + (w >> 2)*2240;
        #pragma unroll
        for (int jj = 0; jj < 8; jj++) {
            float lo, hi; UNPACK2(lo, hi, acc[jj]);
            int jl = joL*8 + jj;
            Ow[(2*lane)*35 + jl]   = lo;
            Ow[(2*lane+1)*35 + jl] = hi;
        }
    }
    __syncthreads();
    #pragma unroll
    for (int r = 0; r < 8; r++) {
        int idx = t + 256*r;                 // row(64) x jl(32)
        int row = idx >> 5, jl = idx & 31;
        float v = sm[row*35 + jl] + sm[2240 + row*35 + jl];
        int sj = sjb[jh*32 + jl];
        out[(size_t)(bg*64 + row)*8192 + (size_t)n*64 + sj] = v;
    }
}

// ---------------------------------------------------------------------------
extern "C" void kernel_launch(void* const* d_in, const int* in_sizes, int n_in,
                              void* d_out, int out_size) {
    const float* x      = (const float*)d_in[0];
    const float* w_gp   = (const float*)d_in[1];
    const float* w_lin  = (const float*)d_in[2];
    const float* b_lin  = (const float*)d_in[3];
    const float* a_norm = (const float*)d_in[4];
    const int*   pidx   = (const int*)d_in[7];
    int P = in_sizes[7] / 3;
    float* out = (float*)d_out;
    (void)n_in; (void)out_size;

    cudaFuncSetAttribute(k_linear,   cudaFuncAttributeMaxDynamicSharedMemorySize, 8960*4);
    cudaFuncSetAttribute(k_bilinear, cudaFuncAttributeMaxDynamicSharedMemorySize, 12544*4);

    k_linear<<<1024, 256, 8960*4>>>(x, w_lin, b_lin, a_norm);
    k_bilinear<<<dim3(128, 2, 4), 256, 12544*4>>>(x, w_gp, pidx, P, out);
}

// round 12
// speedup vs baseline: 1.1196x; 1.1196x over previous
#include <cuda_runtime.h>

#define EPS 1e-6f
typedef unsigned long long u64t;

#define MUL2(d,a,b)    asm("mul.rn.f32x2 %0, %1, %2;" : "=l"(d) : "l"(a), "l"(b))
#define FMA2(d,a,b,c)  asm("fma.rn.f32x2 %0, %1, %2, %3;" : "=l"(d) : "l"(a), "l"(b), "l"(c))
#define PACK2(d,lo,hi) asm("mov.b64 %0, {%1, %2};" : "=l"(d) : "f"(lo), "f"(hi))
#define UNPACK2(lo,hi,s) asm("mov.b64 {%0, %1}, %2;" : "=f"(lo), "=f"(hi) : "l"(s))

// Scratch (device globals: no allocation allowed)
__device__ float g_xr[256*128*64];     // xr in BINARY blade order, 8 MB
__device__ float g_wp[65536];          // w packed for LDG.64 streaming, 256 KB

// ---------------------------------------------------------------------------
// Compile-time blade-ordering tables (input-independent, N_GEN=6 fixed).
struct Tab { int b2s[64]; int s2c[64]; int c2b[64]; int qcls[16]; };

constexpr int popc_c(int v) { int c = 0; while (v) { c += v & 1; v >>= 1; } return c; }

constexpr Tab make_tab() {
    Tab T{};
    int s_of_b[64] = {};
    for (int b = 0; b < 64; b++) {
        int pc = popc_c(b), rank = 0;
        for (int u = 0; u < 64; u++) {
            int pu = popc_c(u);
            if (pu < pc || (pu == pc && u < b)) rank++;
        }
        s_of_b[b] = rank;
        T.b2s[b] = rank;
    }
    for (int b = 0; b < 64; b++) {
        int c = popc_c(b) & 3, s = s_of_b[b], co = 0;
        for (int u = 0; u < 64; u++) {
            int cu = popc_c(u) & 3;
            if (cu < c || (cu == c && s_of_b[u] < s)) co++;
        }
        T.s2c[s] = co;
        T.c2b[co] = b;
        if ((co & 3) == 0) T.qcls[co >> 2] = c;
    }
    return T;
}

__constant__ Tab d_tab = make_tab();

// ---------------------------------------------------------------------------
// Pack w_lin for LDG.64 streaming (gather form, coalesced STG.128):
// g_wp[nt*16384 + mp*256 + slot*8 + c*2 + par] = w_lin[(nt*32+slot)*512 + (2mp+par)*4 + c]
__global__ void k_wpack(const float* __restrict__ w_lin) {
    int o4 = (blockIdx.x*128 + threadIdx.x)*4;        // 128 blocks x 128 thr
    int nt = o4 >> 14, r = o4 & 16383;
    int mp = r >> 8, r2 = r & 255;
    int slot = r2 >> 3, c0 = (r2 >> 1) & 3;           // c0 in {0,2}
    const float* src = w_lin + (nt*32 + slot)*512 + 8*mp + c0;
    float4 v;
    v.x = src[0];     // c0,   par 0
    v.y = src[4];     // c0,   par 1
    v.z = src[1];     // c0+1, par 0
    v.w = src[5];     // c0+1, par 1
    *(float4*)(g_wp + o4) = v;
}

// ---------------------------------------------------------------------------
// Kernel 1: linear mix + bias + class-norm gate, f32x2 over m-pairs.
// grid 1024 = (b:256) x (nt:4 of 32 n), block 256.
// x staged in smem (class-sorted pad-swizzle); w STREAMED from g_wp via
// LDG.64 (lanes 0-15 share a 32B sector). smem = x only -> 4 blocks/SM.
__global__ __launch_bounds__(256, 4) void k_linear(
    const float* __restrict__ x, const float* __restrict__ b_lin,
    const float* __restrict__ a_norm) {
    extern __shared__ float sm[];
    __shared__ int ss2c[64], sc2b[64], sq[16];
    int t = threadIdx.x;
    int b = blockIdx.x >> 2, nt = blockIdx.x & 3;
    if (t < 64) { ss2c[t] = d_tab.s2c[t]; sc2b[t] = d_tab.c2b[t]; }
    if (t >= 64 && t < 80) sq[t - 64] = d_tab.qcls[t - 64];
    __syncthreads();   // ss2c needed for staging

    // stage x with class-sort + pad-swizzle transpose
    {
        const float4* xg = (const float4*)(x + (size_t)b*8192);
        #pragma unroll
        for (int r = 0; r < 8; r++) {
            int idx4 = t + 256*r;
            float4 v = xg[idx4];
            int m = idx4 >> 4, s0 = (idx4 & 15)*4;
            int mp = m >> 1, par = m & 1;
            int co;
            co = ss2c[s0+0]; sm[mp*140 + co*2 + par + ((co>>4)<<2)] = v.x;
            co = ss2c[s0+1]; sm[mp*140 + co*2 + par + ((co>>4)<<2)] = v.y;
            co = ss2c[s0+2]; sm[mp*140 + co*2 + par + ((co>>4)<<2)] = v.z;
            co = ss2c[s0+3]; sm[mp*140 + co*2 + par + ((co>>4)<<2)] = v.w;
        }
    }
    __syncthreads();

    int ig = t & 15, nh = (t >> 4) & 7, qh = t >> 7;
    int c = sq[ig];
    const ulonglong2* px = (const ulonglong2*)sm + ig*2 + (ig >> 2);
    const u64t* gw = (const u64t*)g_wp + nt*8192;
    int wo0 = (nh + 16*qh)*4 + c;
    int wo1 = wo0 + 32;                 // slot + 8

    u64t acc[2][4];
    #pragma unroll
    for (int q = 0; q < 2; q++)
        #pragma unroll
        for (int d = 0; d < 4; d++) acc[q][d] = 0ull;

    #pragma unroll
    for (int mp = 0; mp < 64; mp++) {
        ulonglong2 xa = px[mp*35];
        ulonglong2 xb = px[mp*35 + 1];
        u64t w0 = gw[mp*128 + wo0];
        u64t w1 = gw[mp*128 + wo1];
        FMA2(acc[0][0], xa.x, w0, acc[0][0]);
        FMA2(acc[0][1], xa.y, w0, acc[0][1]);
        FMA2(acc[0][2], xb.x, w0, acc[0][2]);
        FMA2(acc[0][3], xb.y, w0, acc[0][3]);
        FMA2(acc[1][0], xa.x, w1, acc[1][0]);
        FMA2(acc[1][1], xa.y, w1, acc[1][1]);
        FMA2(acc[1][2], xb.x, w1, acc[1][2]);
        FMA2(acc[1][3], xb.y, w1, acc[1][3]);
    }

    float f[2][4];
    #pragma unroll
    for (int q = 0; q < 2; q++)
        #pragma unroll
        for (int d = 0; d < 4; d++) {
            float lo, hi; UNPACK2(lo, hi, acc[q][d]);
            f[q][d] = lo + hi;
        }
    int n0 = nt*32 + nh + 16*qh;
    if (ig == 0) { f[0][0] += b_lin[n0]; f[1][0] += b_lin[n0 + 8]; }

    float v[2][4];
    #pragma unroll
    for (int q = 0; q < 2; q++) {
        float s = f[q][0]*f[q][0] + f[q][1]*f[q][1]
                + f[q][2]*f[q][2] + f[q][3]*f[q][3];
        #pragma unroll
        for (int cc = 0; cc < 4; cc++) v[q][cc] = (c == cc) ? s : 0.f;
    }
    #pragma unroll
    for (int off = 8; off; off >>= 1) {
        #pragma unroll
        for (int q = 0; q < 2; q++)
            #pragma unroll
            for (int cc = 0; cc < 4; cc++)
                v[q][cc] += __shfl_xor_sync(0xffffffffu, v[q][cc], off);
    }
    #pragma unroll
    for (int q = 0; q < 2; q++) {
        int n = n0 + 8*q;
        float vv = (c==0)?v[q][0]:(c==1)?v[q][1]:(c==2)?v[q][2]:v[q][3];
        float gg = 1.f/(1.f + expf(-a_norm[n*4 + c]));
        float inv = 1.f/(gg*(sqrtf(vv) - 1.f) + 1.f + EPS);
        float* o = g_xr + (size_t)b*8192 + (size_t)n*64;
        o[sc2b[ig*4+0]] = f[q][0]*inv;
        o[sc2b[ig*4+1]] = f[q][1]*inv;
        o[sc2b[ig*4+2]] = f[q][2]*inv;
        o[sc2b[ig*4+3]] = f[q][3]*inv;
    }
}

// ---------------------------------------------------------------------------
// Kernel 2: out[b,n,j] = sum_k coef[n][k][j] * x[b,n,j^k] * xr[b,n,k]
// grid (n:128, jh:2, bg:4), block 256 = 8 warps.
// warp w: j-octet = jh*4 + (w&3); ko range = (w>>2)*4 .. +3.
// launch_bounds(256,3): ~85 regs so ptxas can batch loads deep (R11's 64-reg
// cap caused short-scoreboard stalls). rv[8]+xv[8] preloaded per kt so the
// kk loop is pure cc-load + FMA with 16 independent loads in flight.
// smem words: Cs2 dup pairs (j-half) [0,4096); Rp [4096,8320): k*66+2bp;
//             Xp [8320,12544): i*66+2bp.  50.2 KB.
__global__ __launch_bounds__(256, 3) void k_bilinear(
    const float* __restrict__ x, const float* __restrict__ w_gp,
    const int* __restrict__ pidx, int P, float* __restrict__ out) {
    extern __shared__ float sm[];
    __shared__ int sjb[64];
    __shared__ float f4[64];
    int n = blockIdx.x, jh = blockIdx.y, bg = blockIdx.z;
    int t = threadIdx.x;
    if (t < 64) { sjb[t] = d_tab.b2s[t]; f4[t] = 0.f; }
    __syncthreads();

    // fill f4 from paths + stage x/xr (sjb ready)
    for (int p = t; p < P; p += 256) {
        int code = pidx[3*p]*16 + pidx[3*p+1]*4 + pidx[3*p+2];
        f4[code] = w_gp[n*P + p];
    }
    #pragma unroll
    for (int r = 0; r < 8; r++) {
        int p = t + 256*r;
        int i = p & 63, bq = p >> 6;
        size_t gb = (size_t)(bg*64 + 2*bq)*8192 + (size_t)n*64;
        int s = sjb[i];
        float xl = x[gb + s],      xh = x[gb + 8192 + s];
        float rl = g_xr[gb + i],   rh = g_xr[gb + 8192 + i];
        u64t pxv, prv; PACK2(pxv, xl, xh); PACK2(prv, rl, rh);
        *(u64t*)(sm + 8320 + i*66 + 2*bq) = pxv;
        *(u64t*)(sm + 4096 + i*66 + 2*bq) = prv;
    }
    __syncthreads();

    // compute coef dup-pairs for this j-half (reads f4, writes [0,4096) words)
    u64t* Cs2 = (u64t*)sm;
    #pragma unroll
    for (int r = 0; r < 8; r++) {
        int idx = t + 256*r;                 // idx = k*32 + jl
        int k = idx >> 5, jl = idx & 31;
        int j = jh*32 + jl, i = j ^ k;
        int h = (i>>1) ^ (i>>2) ^ (i>>3) ^ (i>>4) ^ (i>>5);
        float sgn = (__popc(h & k) & 1) ? -1.f : 1.f;
        int code = (__popc(i)&3)*16 + (__popc(j)&3)*4 + (__popc(k)&3);
        float c = sgn * f4[code];
        u64t pc; PACK2(pc, c, c);
        Cs2[idx] = pc;
    }
    __syncthreads();

    int lane = t & 31, w = t >> 5;
    int joL = w & 3;                 // local j-octet within half
    int jog = jh*4 + joL;            // global j-octet
    int kb = (w >> 2)*4;             // ko range start
    const u64t* pR = (const u64t*)sm + 2048 + lane;   // + k*33
    const u64t* pX = (const u64t*)sm + 4160 + lane;   // + i*33
    const ulonglong2* pC = (const ulonglong2*)sm;     // + k*16 + joL*4 + jp

    u64t acc[8];
    #pragma unroll
    for (int jj = 0; jj < 8; jj++) acc[jj] = 0ull;

    #pragma unroll
    for (int kt = 0; kt < 4; kt++) {
        int ko = kb + kt;
        int io = jog ^ ko;
        u64t xv[8], rv[8];
        #pragma unroll
        for (int d = 0; d < 8; d++) xv[d] = pX[(io*8 + d)*33];
        #pragma unroll
        for (int kk = 0; kk < 8; kk++) rv[kk] = pR[(ko*8 + kk)*33];
        #pragma unroll
        for (int kk = 0; kk < 8; kk++) {
            const ulonglong2* pCk = pC + (ko*8 + kk)*16 + joL*4;
            #pragma unroll
            for (int jp = 0; jp < 4; jp++) {
                ulonglong2 cc = pCk[jp];
                u64t t0, t1;
                MUL2(t0, xv[(2*jp)^kk], rv[kk]);
                FMA2(acc[2*jp], cc.x, t0, acc[2*jp]);
                MUL2(t1, xv[(2*jp+1)^kk], rv[kk]);
                FMA2(acc[2*jp+1], cc.y, t1, acc[2*jp+1]);
            }
        }
    }
    __syncthreads();
    // two partial buffers: warps 0-3 -> [0,2240), warps 4-7 -> [2240,4480)
    {
        float* Ow = sm + (w >> 2)*2240;
        #pragma unroll
        for (int jj = 0; jj < 8; jj++) {
            float lo, hi; UNPACK2(lo, hi, acc[jj]);
            int jl = joL*8 + jj;
            Ow[(2*lane)*35 + jl]   = lo;
            Ow[(2*lane+1)*35 + jl] = hi;
        }
    }
    __syncthreads();
    #pragma unroll
    for (int r = 0; r < 8; r++) {
        int idx = t + 256*r;                 // row(64) x jl(32)
        int row = idx >> 5, jl = idx & 31;
        float v = sm[row*35 + jl] + sm[2240 + row*35 + jl];
        int sj = sjb[jh*32 + jl];
        out[(size_t)(bg*64 + row)*8192 + (size_t)n*64 + sj] = v;
    }
}

// ---------------------------------------------------------------------------
extern "C" void kernel_launch(void* const* d_in, const int* in_sizes, int n_in,
                              void* d_out, int out_size) {
    const float* x      = (const float*)d_in[0];
    const float* w_gp   = (const float*)d_in[1];
    const float* w_lin  = (const float*)d_in[2];
    const float* b_lin  = (const float*)d_in[3];
    const float* a_norm = (const float*)d_in[4];
    const int*   pidx   = (const int*)d_in[7];
    int P = in_sizes[7] / 3;
    float* out = (float*)d_out;
    (void)n_in; (void)out_size;

    cudaFuncSetAttribute(k_linear,   cudaFuncAttributeMaxDynamicSharedMemorySize, 8960*4);
    cudaFuncSetAttribute(k_bilinear, cudaFuncAttributeMaxDynamicSharedMemorySize, 12544*4);

    k_wpack<<<128, 128>>>(w_lin);
    k_linear<<<1024, 256, 8960*4>>>(x, b_lin, a_norm);
    k_bilinear<<<dim3(128, 2, 4), 256, 12544*4>>>(x, w_gp, pidx, P, out);
}